// round 5
// baseline (speedup 1.0000x reference)
#include <cuda_runtime.h>
#include <cstdint>
#include <cstddef>

#define BB 4096
#define TT 32
#define AA 4
#define OBSD 115
#define HH 64
#define KK 8
#define ACTN 19
#define FEATN 23
#define INDIM 99
#define NBLK 128

// x_all scratch: [T][B][H] fp32 = 33.5 MB
__device__ float g_xall[(size_t)TT * BB * HH];
// precomputed layer-0 input gates (+bih0): [t][blk][j][gate][row]
__device__ float g_gi[(size_t)TT * NBLK * 64 * 96];

// ---------------- helpers ----------------
__device__ __forceinline__ unsigned long long ffma2(unsigned long long a,
                                                    unsigned long long b,
                                                    unsigned long long c) {
    unsigned long long d;
    asm("fma.rn.f32x2 %0, %1, %2, %3;" : "=l"(d) : "l"(a), "l"(b), "l"(c));
    return d;
}
__device__ __forceinline__ unsigned long long pack2(float lo, float hi) {
    unsigned long long d;
    asm("mov.b64 %0, {%1, %2};" : "=l"(d) : "f"(lo), "f"(hi));
    return d;
}
__device__ __forceinline__ float sumh(unsigned long long v) {
    float lo = __uint_as_float((unsigned)(v & 0xffffffffull));
    float hi = __uint_as_float((unsigned)(v >> 32));
    return lo + hi;
}
__device__ __forceinline__ float sigf(float x) {
    return __fdividef(1.f, 1.f + __expf(-x));
}
__device__ __forceinline__ float tanhf_fast(float x) {
    return __fdividef(2.f, 1.f + __expf(-2.f * x)) - 1.f;
}

// ---------------- kernel 1: features + projection + LN + ReLU ----------------
// phase 1: one task per THREAD computes 23 features + 4 onehot cols (no lane
// replication); phase 2: each warp projects its 32 tasks with f32x2 math.
// dyn smem: pTp 25344 | params 768 | fbuf 25600 | abuf 4096 = 55808
#define KF_PT 0
#define KF_PAR 25344
#define KF_FB (25344 + 768)
#define KF_AB (KF_FB + 25600)
#define KF_SMEM (KF_AB + 4096)

__global__ __launch_bounds__(256) void k_feat(const float* __restrict__ obs,
                                              const int* __restrict__ act,
                                              const float* __restrict__ pW,
                                              const float* __restrict__ pb,
                                              const float* __restrict__ lg,
                                              const float* __restrict__ lb) {
    extern __shared__ char smc[];
    float2* pTp = (float2*)(smc + KF_PT);      // [f][hp] pair of h=2hp,2hp+1
    float2* sbp = (float2*)(smc + KF_PAR);     // proj bias pairs [32]
    float2* sgp = sbp + 32;                    // ln gamma pairs
    float2* sbtp = sbp + 64;                   // ln beta pairs
    float* fbuf = (float*)(smc + KF_FB);       // [task][25]
    int* abuf = (int*)(smc + KF_AB);           // [task][4] onehot col index

    int tid = threadIdx.x;
    for (int i = tid; i < INDIM * 32; i += 256) {
        int f = i >> 5, hp = i & 31;
        pTp[i] = make_float2(pW[(2 * hp) * INDIM + f], pW[(2 * hp + 1) * INDIM + f]);
    }
    if (tid < 32) {
        sbp[tid] = make_float2(pb[2 * tid], pb[2 * tid + 1]);
        sgp[tid] = make_float2(lg[2 * tid], lg[2 * tid + 1]);
        sbtp[tid] = make_float2(lb[2 * tid], lb[2 * tid + 1]);
    }

    // ---- phase 1: per-thread feature extraction ----
    {
        int task = blockIdx.x * 256 + tid;
        int b = task >> 5, t = task & 31;
        const float* o = obs + (size_t)(b * TT + t) * AA * OBSD;
        float px[AA], py[AA];
#pragma unroll
        for (int a = 0; a < AA; a++) { px[a] = o[a * OBSD]; py[a] = o[a * OBSD + 1]; }
        float bx = o[88], by = o[89];
        float bvx = 0.f, bvy = 0.f;
        if (t > 0) { bvx = bx - o[88 - AA * OBSD]; bvy = by - o[89 - AA * OBSD]; }
        float cx = 0.25f * (px[0] + px[1] + px[2] + px[3]);
        float cy = 0.25f * (py[0] + py[1] + py[2] + py[3]);
        float sp = 0.f;
#pragma unroll
        for (int a = 0; a < AA; a++) {
            float dx = px[a] - cx, dy = py[a] - cy;
            sp += dx * dx + dy * dy;
        }
        float spread = sqrtf(0.25f * sp + 1e-6f);
        float* fb = fbuf + tid * 25;
        fb[0] = bx; fb[1] = by; fb[2] = bvx; fb[3] = bvy;
#pragma unroll
        for (int a = 0; a < AA; a++) { fb[4 + 2 * a] = px[a]; fb[5 + 2 * a] = py[a]; }
        fb[12] = cx; fb[13] = cy; fb[14] = spread;
#pragma unroll
        for (int i = 0; i < AA; i++) {
            float best = 3.4e38f; int bj = 0;
#pragma unroll
            for (int j = 0; j < AA; j++) {
                if (j == i) continue;
                float dx = px[i] - px[j], dy = py[i] - py[j];
                float d = dx * dx + dy * dy;
                if (d < best) { best = d; bj = j; }
            }
            fb[15 + 2 * i] = px[bj] - px[i];
            fb[16 + 2 * i] = py[bj] - py[i];
        }
        const int* ap = act + (b * TT + t) * AA;
#pragma unroll
        for (int a = 0; a < AA; a++) abuf[tid * 4 + a] = FEATN + a * ACTN + ap[a];
    }
    __syncthreads();

    // ---- phase 2: warp projects its 32 tasks ----
    int lane = tid & 31, w = tid >> 5;
    const unsigned long long* pTq = (const unsigned long long*)pTp;
    unsigned long long bini = *(const unsigned long long*)&sbp[lane];
    for (int tt = 0; tt < 32; tt++) {
        int s = w * 32 + tt;
        const float* fb = fbuf + s * 25;
        unsigned long long acc = bini;
#pragma unroll
        for (int f = 0; f < FEATN; f++) {
            float x = fb[f];
            acc = ffma2(pack2(x, x), pTq[f * 32 + lane], acc);
        }
        unsigned long long one2 = pack2(1.f, 1.f);
#pragma unroll
        for (int a = 0; a < AA; a++) {
            int col = abuf[s * 4 + a];
            acc = ffma2(one2, pTq[col * 32 + lane], acc);
        }
        float a0 = __uint_as_float((unsigned)(acc & 0xffffffffull));
        float a1 = __uint_as_float((unsigned)(acc >> 32));
        float sm = a0 + a1;
#pragma unroll
        for (int off = 16; off; off >>= 1) sm += __shfl_xor_sync(0xffffffffu, sm, off);
        float mu = sm * (1.f / 64.f);
        float d0 = a0 - mu, d1 = a1 - mu;
        float v = d0 * d0 + d1 * d1;
#pragma unroll
        for (int off = 16; off; off >>= 1) v += __shfl_xor_sync(0xffffffffu, v, off);
        float sc = rsqrtf(v * (1.f / 64.f) + 1e-5f);
        float2 g = sgp[lane], bt = sbtp[lane];
        float y0 = fmaxf(fmaf(d0 * sc, g.x, bt.x), 0.f);
        float y1 = fmaxf(fmaf(d1 * sc, g.y, bt.y), 0.f);
        int task = blockIdx.x * 256 + s;
        int b = task >> 5, t = task & 31;
        *(float2*)(g_xall + ((size_t)t * BB + b) * HH + 2 * lane) = make_float2(y0, y1);
    }
}

// ---------------- kernel 2: parallel layer-0 input-gate GEMM ----------------
// 512 blocks: (t-chunk of 8) x (128 batch tiles)
#define GI_SMEM 74752
__global__ __launch_bounds__(256, 1) void k_gi0(const float* __restrict__ Wih0,
                                                const float* __restrict__ bih0) {
    extern __shared__ char smc[];
    float2* wq = (float2*)smc;                    // [j][kp][4] float2 (r,z,n,pad)
    float2* xs = (float2*)(smc + 65536);          // [kp][r] padded 33
    float* sbi = (float*)(smc + 65536 + 8448);    // bih0[192]

    int tid = threadIdx.x;
    for (int i = tid; i < 64 * 32 * 4; i += 256) {
        int j = i >> 7, kp = (i >> 2) & 31, m = i & 3;
        float2 v = make_float2(0.f, 0.f);
        if (m < 3) {
            const float* src = Wih0 + (size_t)(m * 64 + j) * 64 + 2 * kp;
            v.x = src[0]; v.y = src[1];
        }
        wq[i] = v;
    }
    if (tid < 192) sbi[tid] = bih0[tid];

    int r = tid & 31, w = tid >> 5, jbase = w * 8;
    int blk = blockIdx.x & 127, tchunk = blockIdx.x >> 7;
    int rowbase = blk * 32;

    for (int tq = 0; tq < 8; tq++) {
        int t = tchunk * 8 + tq;
        __syncthreads();
        for (int i = tid; i < 1024; i += 256) {
            int rr = i >> 5, kp = i & 31;
            const float2* src =
                (const float2*)(g_xall + ((size_t)t * BB + rowbase + rr) * HH) + kp;
            xs[kp * 33 + rr] = *src;
        }
        __syncthreads();
        unsigned long long acc[24];
#pragma unroll
        for (int i = 0; i < 24; i++) acc[i] = 0ull;
#pragma unroll
        for (int kp = 0; kp < 32; kp++) {
            unsigned long long x2 = *(const unsigned long long*)&xs[kp * 33 + r];
#pragma unroll
            for (int j = 0; j < 8; j++) {
                const ulonglong2* wp = (const ulonglong2*)&wq[((jbase + j) * 32 + kp) * 4];
                ulonglong2 wa = wp[0];
                ulonglong2 wb = wp[1];
                acc[j * 3 + 0] = ffma2(x2, wa.x, acc[j * 3 + 0]);
                acc[j * 3 + 1] = ffma2(x2, wa.y, acc[j * 3 + 1]);
                acc[j * 3 + 2] = ffma2(x2, wb.x, acc[j * 3 + 2]);
            }
        }
        float* gout = g_gi + ((size_t)(t * NBLK + blk) * 64) * 96;
#pragma unroll
        for (int j = 0; j < 8; j++) {
            int jj = jbase + j;
#pragma unroll
            for (int m = 0; m < 3; m++)
                gout[jj * 96 + m * 32 + r] = sumh(acc[j * 3 + m]) + sbi[m * 64 + jj];
        }
    }
}

// ---------------- kernel 3: fused 2-layer GRU recurrence + classifier ----------------
// 512 threads / 16 warps, 4 hidden dims per warp, ONE barrier per phase
// (layer0 step t and layer1 step t-1 both read only p-buffers).
// smem: wb0 65536 | wb1 98304 | hb 32768 | bias0 1024 | bias1 1024 = 198656
#define SM_WB1 65536
#define SM_HB (65536 + 98304)
#define SM_B0 (SM_HB + 32768)
#define SM_B1 (SM_B0 + 1024)
#define SMEM_TOTAL (SM_B1 + 1024)

__global__ __launch_bounds__(512, 1) void k_gru(
    const float* __restrict__ Whh0, const float* __restrict__ bhh0,
    const float* __restrict__ Wih1, const float* __restrict__ Whh1,
    const float* __restrict__ bih1, const float* __restrict__ bhh1,
    const float* __restrict__ cW1, const float* __restrict__ cb1,
    const float* __restrict__ cW2, const float* __restrict__ cb2,
    float* __restrict__ out) {
    extern __shared__ char smc[];
    float2* wb0 = (float2*)smc;              // [j][kp][4] float2: Whh0 r,z,n,pad
    float2* wb1 = (float2*)(smc + SM_WB1);   // [j][kp][6] float2
    float2* hb = (float2*)(smc + SM_HB);     // 4 buffers of [kp][r] float2
    float4* bias0 = (float4*)(smc + SM_B0);
    float4* bias1 = (float4*)(smc + SM_B1);

    int tid = threadIdx.x;
    int r = tid & 31;
    int w = tid >> 5;        // 0..15
    int jbase = w * 4;       // 4 hidden dims per warp

    // ---- stage weights ----
    for (int i = tid; i < 64 * 32 * 4; i += 512) {
        int j = i >> 7, kp = (i >> 2) & 31, m = i & 3;
        float2 v = make_float2(0.f, 0.f);
        if (m < 3) {
            const float* src = Whh0 + (size_t)(m * 64 + j) * 64 + 2 * kp;
            v.x = src[0]; v.y = src[1];
        }
        wb0[i] = v;
    }
    for (int i = tid; i < 64 * 32 * 6; i += 512) {
        int m = i % 6;
        int kp = (i / 6) & 31;
        int j = i / 192;
        int g = (m >> 1) * 64 + j;
        const float* src = (m & 1) ? Whh1 : Wih1;
        float2 v;
        v.x = src[g * 64 + 2 * kp];
        v.y = src[g * 64 + 2 * kp + 1];
        wb1[i] = v;
    }
    if (tid < 64) {
        bias0[tid] = make_float4(bhh0[tid], bhh0[64 + tid], bhh0[128 + tid], 0.f);
        bias1[tid] = make_float4(bih1[tid] + bhh1[tid], bih1[64 + tid] + bhh1[64 + tid],
                                 bih1[128 + tid], bhh1[128 + tid]);
    }
    for (int i = tid; i < 4 * 1024; i += 512) hb[i] = make_float2(0.f, 0.f);
    __syncthreads();

    int blk = blockIdx.x;
    int rowbase = blk * 32;
    const float2* wl0 = wb0 + (size_t)jbase * 32 * 4;
    const float2* wl1 = wb1 + (size_t)jbase * 32 * 6;

    // prefetch gi for t=0
    float gcur[12];
    {
        const float* gp = g_gi + ((size_t)(0 * NBLK + blk) * 64) * 96 + r;
#pragma unroll
        for (int j = 0; j < 4; j++)
#pragma unroll
            for (int m = 0; m < 3; m++)
                gcur[j * 3 + m] = gp[(jbase + j) * 96 + m * 32];
    }

    int p = 0;
    for (int t = 0; t <= TT; t++) {
        // ===== layer 0, step t: h0[p] -> h0[p^1] =====
        if (t < TT) {
            unsigned long long aR[4], aZ[4], aN[4];
#pragma unroll
            for (int j = 0; j < 4; j++) { aR[j] = aZ[j] = aN[j] = 0ull; }
            const unsigned long long* h0p = (const unsigned long long*)(hb + p * 1024);
#pragma unroll
            for (int kp = 0; kp < 32; kp++) {
                unsigned long long h2 = h0p[kp * 32 + r];
#pragma unroll
                for (int j = 0; j < 4; j++) {
                    const ulonglong2* wp = (const ulonglong2*)(wl0 + (size_t)((j * 32 + kp) * 4));
                    ulonglong2 wa = wp[0];
                    ulonglong2 wb = wp[1];
                    aR[j] = ffma2(h2, wa.x, aR[j]);
                    aZ[j] = ffma2(h2, wa.y, aZ[j]);
                    aN[j] = ffma2(h2, wb.x, aN[j]);
                }
            }
            float* hnew = (float*)(hb + (p ^ 1) * 1024);
            const float* hold = (const float*)(hb + p * 1024);
#pragma unroll
            for (int j = 0; j < 4; j++) {
                int jj = jbase + j;
                float4 bv = bias0[jj];
                float rg = sigf(gcur[j * 3 + 0] + sumh(aR[j]) + bv.x);
                float zg = sigf(gcur[j * 3 + 1] + sumh(aZ[j]) + bv.y);
                float ng = tanhf_fast(gcur[j * 3 + 2] + rg * (sumh(aN[j]) + bv.z));
                float ho = hold[(jj >> 1) * 64 + r * 2 + (jj & 1)];
                hnew[(jj >> 1) * 64 + r * 2 + (jj & 1)] = ng + zg * (ho - ng);
            }
        }
        // prefetch gi for t+1
        if (t + 1 < TT) {
            const float* gp = g_gi + ((size_t)((t + 1) * NBLK + blk) * 64) * 96 + r;
#pragma unroll
            for (int j = 0; j < 4; j++)
#pragma unroll
                for (int m = 0; m < 3; m++)
                    gcur[j * 3 + m] = gp[(jbase + j) * 96 + m * 32];
        }
        // ===== layer 1, step t-1: x = h0[p] (= ys0[t-1]), h1[p] -> h1[p^1] =====
        if (t > 0) {
            unsigned long long ar[4], az[4], ai[4], ah[4];
#pragma unroll
            for (int j = 0; j < 4; j++) { ar[j] = az[j] = ai[j] = ah[j] = 0ull; }
            const unsigned long long* x1p = (const unsigned long long*)(hb + p * 1024);
            const unsigned long long* h1p = (const unsigned long long*)(hb + (2 + p) * 1024);
#pragma unroll
            for (int kp = 0; kp < 32; kp++) {
                unsigned long long x2 = x1p[kp * 32 + r];
                unsigned long long h2 = h1p[kp * 32 + r];
#pragma unroll
                for (int j = 0; j < 4; j++) {
                    const ulonglong2* wp = (const ulonglong2*)(wl1 + (size_t)((j * 32 + kp) * 6));
                    ulonglong2 wa = wp[0];
                    ulonglong2 wb = wp[1];
                    ulonglong2 wc = wp[2];
                    ar[j] = ffma2(x2, wa.x, ar[j]); ar[j] = ffma2(h2, wa.y, ar[j]);
                    az[j] = ffma2(x2, wb.x, az[j]); az[j] = ffma2(h2, wb.y, az[j]);
                    ai[j] = ffma2(x2, wc.x, ai[j]);
                    ah[j] = ffma2(h2, wc.y, ah[j]);
                }
            }
            float* hnew = (float*)(hb + (2 + (p ^ 1)) * 1024);
            const float* hold = (const float*)(hb + (2 + p) * 1024);
#pragma unroll
            for (int j = 0; j < 4; j++) {
                int jj = jbase + j;
                float4 bv = bias1[jj];
                float rg = sigf(sumh(ar[j]) + bv.x);
                float zg = sigf(sumh(az[j]) + bv.y);
                float ng = tanhf_fast(sumh(ai[j]) + bv.z + rg * (sumh(ah[j]) + bv.w));
                float ho = hold[(jj >> 1) * 64 + r * 2 + (jj & 1)];
                hnew[(jj >> 1) * 64 + r * 2 + (jj & 1)] = ng + zg * (ho - ng);
            }
        }
        __syncthreads();
        p ^= 1;
    }

    // ===== classifier: hid = relu(h1 @ cls_W1.T + b1) ; logits = hid @ cls_W2.T + b2 =====
    {
        unsigned long long acc[4];
#pragma unroll
        for (int j = 0; j < 4; j++) acc[j] = 0ull;
        const unsigned long long* h1p = (const unsigned long long*)(hb + (2 + p) * 1024);
#pragma unroll
        for (int kp = 0; kp < 32; kp++) {
            unsigned long long h2 = h1p[kp * 32 + r];
#pragma unroll
            for (int j = 0; j < 4; j++) {
                const unsigned long long* wp =
                    (const unsigned long long*)(cW1 + (jbase + j) * 64 + 2 * kp);
                acc[j] = ffma2(h2, *wp, acc[j]);
            }
        }
        float* hidb = (float*)(hb + (p ^ 1) * 1024);   // dead h0 buffer
#pragma unroll
        for (int j = 0; j < 4; j++) {
            int jj = jbase + j;
            float hv = fmaxf(sumh(acc[j]) + cb1[jj], 0.f);
            hidb[(jj >> 1) * 64 + r * 2 + (jj & 1)] = hv;
        }
    }
    __syncthreads();
    if (w < 8) {
        unsigned long long a = 0ull;
        const unsigned long long* hp = (const unsigned long long*)(hb + (p ^ 1) * 1024);
#pragma unroll
        for (int kp = 0; kp < 32; kp++) {
            const unsigned long long* wp = (const unsigned long long*)(cW2 + w * 64 + 2 * kp);
            a = ffma2(hp[kp * 32 + r], *wp, a);
        }
        out[(rowbase + r) * 8 + w] = sumh(a) + cb2[w];
    }
}

// ---------------- launch ----------------
extern "C" void kernel_launch(void* const* d_in, const int* in_sizes, int n_in,
                              void* d_out, int out_size) {
    const float* obs  = (const float*)d_in[0];
    const int*   act  = (const int*)d_in[1];
    const float* pW   = (const float*)d_in[2];
    const float* pb   = (const float*)d_in[3];
    const float* lg   = (const float*)d_in[4];
    const float* lb   = (const float*)d_in[5];
    const float* Wih0 = (const float*)d_in[6];
    const float* Whh0 = (const float*)d_in[7];
    const float* bih0 = (const float*)d_in[8];
    const float* bhh0 = (const float*)d_in[9];
    const float* Wih1 = (const float*)d_in[10];
    const float* Whh1 = (const float*)d_in[11];
    const float* bih1 = (const float*)d_in[12];
    const float* bhh1 = (const float*)d_in[13];
    const float* cW1  = (const float*)d_in[14];
    const float* cb1  = (const float*)d_in[15];
    const float* cW2  = (const float*)d_in[16];
    const float* cb2  = (const float*)d_in[17];
    float* out = (float*)d_out;

    cudaFuncSetAttribute(k_feat, cudaFuncAttributeMaxDynamicSharedMemorySize, KF_SMEM);
    cudaFuncSetAttribute(k_gi0, cudaFuncAttributeMaxDynamicSharedMemorySize, GI_SMEM);
    cudaFuncSetAttribute(k_gru, cudaFuncAttributeMaxDynamicSharedMemorySize, SMEM_TOTAL);

    k_feat<<<512, 256, KF_SMEM>>>(obs, act, pW, pb, lg, lb);
    k_gi0<<<512, 256, GI_SMEM>>>(Wih0, bih0);
    k_gru<<<NBLK, 512, SMEM_TOTAL>>>(Whh0, bhh0,
                                     Wih1, Whh1, bih1, bhh1,
                                     cW1, cb1, cW2, cb2, out);
}

// round 6
// speedup vs baseline: 1.0064x; 1.0064x over previous
#include <cuda_runtime.h>
#include <cstdint>
#include <cstddef>

#define BB 4096
#define TT 32
#define AA 4
#define OBSD 115
#define HH 64
#define KK 8
#define ACTN 19
#define FEATN 23
#define INDIM 99
#define NBLK 128

// x_all scratch: [T][B][H] fp32 = 33.5 MB
__device__ float g_xall[(size_t)TT * BB * HH];
// precomputed layer-0 input gates (+bih0): [t][blk][j][gate][row]
__device__ float g_gi[(size_t)TT * NBLK * 64 * 96];

// ---------------- helpers ----------------
__device__ __forceinline__ unsigned long long ffma2(unsigned long long a,
                                                    unsigned long long b,
                                                    unsigned long long c) {
    unsigned long long d;
    asm("fma.rn.f32x2 %0, %1, %2, %3;" : "=l"(d) : "l"(a), "l"(b), "l"(c));
    return d;
}
__device__ __forceinline__ unsigned long long pack2(float lo, float hi) {
    unsigned long long d;
    asm("mov.b64 %0, {%1, %2};" : "=l"(d) : "f"(lo), "f"(hi));
    return d;
}
__device__ __forceinline__ float sumh(unsigned long long v) {
    float lo = __uint_as_float((unsigned)(v & 0xffffffffull));
    float hi = __uint_as_float((unsigned)(v >> 32));
    return lo + hi;
}
__device__ __forceinline__ float sigf(float x) {
    return __fdividef(1.f, 1.f + __expf(-x));
}
__device__ __forceinline__ float tanhf_fast(float x) {
    return __fdividef(2.f, 1.f + __expf(-2.f * x)) - 1.f;
}

// ---------------- kernel 1: features + projection + LN + ReLU ----------------
// phase 1: one task per THREAD computes 23 features + 4 onehot cols (no lane
// replication); phase 2: each warp projects its 32 tasks with f32x2 math.
// dyn smem: pTp 25344 | params 768 | fbuf 25600 | abuf 4096 = 55808
#define KF_PT 0
#define KF_PAR 25344
#define KF_FB (25344 + 768)
#define KF_AB (KF_FB + 25600)
#define KF_SMEM (KF_AB + 4096)

__global__ __launch_bounds__(256) void k_feat(const float* __restrict__ obs,
                                              const int* __restrict__ act,
                                              const float* __restrict__ pW,
                                              const float* __restrict__ pb,
                                              const float* __restrict__ lg,
                                              const float* __restrict__ lb) {
    extern __shared__ char smc[];
    float2* pTp = (float2*)(smc + KF_PT);      // [f][hp] pair of h=2hp,2hp+1
    float2* sbp = (float2*)(smc + KF_PAR);     // proj bias pairs [32]
    float2* sgp = sbp + 32;                    // ln gamma pairs
    float2* sbtp = sbp + 64;                   // ln beta pairs
    float* fbuf = (float*)(smc + KF_FB);       // [task][25]
    int* abuf = (int*)(smc + KF_AB);           // [task][4] onehot col index

    int tid = threadIdx.x;
    for (int i = tid; i < INDIM * 32; i += 256) {
        int f = i >> 5, hp = i & 31;
        pTp[i] = make_float2(pW[(2 * hp) * INDIM + f], pW[(2 * hp + 1) * INDIM + f]);
    }
    if (tid < 32) {
        sbp[tid] = make_float2(pb[2 * tid], pb[2 * tid + 1]);
        sgp[tid] = make_float2(lg[2 * tid], lg[2 * tid + 1]);
        sbtp[tid] = make_float2(lb[2 * tid], lb[2 * tid + 1]);
    }

    // ---- phase 1: per-thread feature extraction ----
    {
        int task = blockIdx.x * 256 + tid;
        int b = task >> 5, t = task & 31;
        const float* o = obs + (size_t)(b * TT + t) * AA * OBSD;
        float px[AA], py[AA];
#pragma unroll
        for (int a = 0; a < AA; a++) { px[a] = o[a * OBSD]; py[a] = o[a * OBSD + 1]; }
        float bx = o[88], by = o[89];
        float bvx = 0.f, bvy = 0.f;
        if (t > 0) { bvx = bx - o[88 - AA * OBSD]; bvy = by - o[89 - AA * OBSD]; }
        float cx = 0.25f * (px[0] + px[1] + px[2] + px[3]);
        float cy = 0.25f * (py[0] + py[1] + py[2] + py[3]);
        float sp = 0.f;
#pragma unroll
        for (int a = 0; a < AA; a++) {
            float dx = px[a] - cx, dy = py[a] - cy;
            sp += dx * dx + dy * dy;
        }
        float spread = sqrtf(0.25f * sp + 1e-6f);
        float* fb = fbuf + tid * 25;
        fb[0] = bx; fb[1] = by; fb[2] = bvx; fb[3] = bvy;
#pragma unroll
        for (int a = 0; a < AA; a++) { fb[4 + 2 * a] = px[a]; fb[5 + 2 * a] = py[a]; }
        fb[12] = cx; fb[13] = cy; fb[14] = spread;
#pragma unroll
        for (int i = 0; i < AA; i++) {
            float best = 3.4e38f; int bj = 0;
#pragma unroll
            for (int j = 0; j < AA; j++) {
                if (j == i) continue;
                float dx = px[i] - px[j], dy = py[i] - py[j];
                float d = dx * dx + dy * dy;
                if (d < best) { best = d; bj = j; }
            }
            fb[15 + 2 * i] = px[bj] - px[i];
            fb[16 + 2 * i] = py[bj] - py[i];
        }
        const int* ap = act + (b * TT + t) * AA;
#pragma unroll
        for (int a = 0; a < AA; a++) abuf[tid * 4 + a] = FEATN + a * ACTN + ap[a];
    }
    __syncthreads();

    // ---- phase 2: warp projects its 32 tasks ----
    int lane = tid & 31, w = tid >> 5;
    const unsigned long long* pTq = (const unsigned long long*)pTp;
    unsigned long long bini = *(const unsigned long long*)&sbp[lane];
    for (int tt = 0; tt < 32; tt++) {
        int s = w * 32 + tt;
        const float* fb = fbuf + s * 25;
        unsigned long long acc = bini;
#pragma unroll
        for (int f = 0; f < FEATN; f++) {
            float x = fb[f];
            acc = ffma2(pack2(x, x), pTq[f * 32 + lane], acc);
        }
        unsigned long long one2 = pack2(1.f, 1.f);
#pragma unroll
        for (int a = 0; a < AA; a++) {
            int col = abuf[s * 4 + a];
            acc = ffma2(one2, pTq[col * 32 + lane], acc);
        }
        float a0 = __uint_as_float((unsigned)(acc & 0xffffffffull));
        float a1 = __uint_as_float((unsigned)(acc >> 32));
        float sm = a0 + a1;
#pragma unroll
        for (int off = 16; off; off >>= 1) sm += __shfl_xor_sync(0xffffffffu, sm, off);
        float mu = sm * (1.f / 64.f);
        float d0 = a0 - mu, d1 = a1 - mu;
        float v = d0 * d0 + d1 * d1;
#pragma unroll
        for (int off = 16; off; off >>= 1) v += __shfl_xor_sync(0xffffffffu, v, off);
        float sc = rsqrtf(v * (1.f / 64.f) + 1e-5f);
        float2 g = sgp[lane], bt = sbtp[lane];
        float y0 = fmaxf(fmaf(d0 * sc, g.x, bt.x), 0.f);
        float y1 = fmaxf(fmaf(d1 * sc, g.y, bt.y), 0.f);
        int task = blockIdx.x * 256 + s;
        int b = task >> 5, t = task & 31;
        *(float2*)(g_xall + ((size_t)t * BB + b) * HH + 2 * lane) = make_float2(y0, y1);
    }
}

// ---------------- kernel 2: parallel layer-0 input-gate GEMM ----------------
// 512 blocks: (t-chunk of 8) x (128 batch tiles)
#define GI_SMEM 74752
__global__ __launch_bounds__(256, 1) void k_gi0(const float* __restrict__ Wih0,
                                                const float* __restrict__ bih0) {
    extern __shared__ char smc[];
    float2* wq = (float2*)smc;                    // [j][kp][4] float2 (r,z,n,pad)
    float2* xs = (float2*)(smc + 65536);          // [kp][r] padded 33
    float* sbi = (float*)(smc + 65536 + 8448);    // bih0[192]

    int tid = threadIdx.x;
    for (int i = tid; i < 64 * 32 * 4; i += 256) {
        int j = i >> 7, kp = (i >> 2) & 31, m = i & 3;
        float2 v = make_float2(0.f, 0.f);
        if (m < 3) {
            const float* src = Wih0 + (size_t)(m * 64 + j) * 64 + 2 * kp;
            v.x = src[0]; v.y = src[1];
        }
        wq[i] = v;
    }
    if (tid < 192) sbi[tid] = bih0[tid];

    int r = tid & 31, w = tid >> 5, jbase = w * 8;
    int blk = blockIdx.x & 127, tchunk = blockIdx.x >> 7;
    int rowbase = blk * 32;

    for (int tq = 0; tq < 8; tq++) {
        int t = tchunk * 8 + tq;
        __syncthreads();
        for (int i = tid; i < 1024; i += 256) {
            int rr = i >> 5, kp = i & 31;
            const float2* src =
                (const float2*)(g_xall + ((size_t)t * BB + rowbase + rr) * HH) + kp;
            xs[kp * 33 + rr] = *src;
        }
        __syncthreads();
        unsigned long long acc[24];
#pragma unroll
        for (int i = 0; i < 24; i++) acc[i] = 0ull;
#pragma unroll
        for (int kp = 0; kp < 32; kp++) {
            unsigned long long x2 = *(const unsigned long long*)&xs[kp * 33 + r];
#pragma unroll
            for (int j = 0; j < 8; j++) {
                const ulonglong2* wp = (const ulonglong2*)&wq[((jbase + j) * 32 + kp) * 4];
                ulonglong2 wa = wp[0];
                ulonglong2 wb = wp[1];
                acc[j * 3 + 0] = ffma2(x2, wa.x, acc[j * 3 + 0]);
                acc[j * 3 + 1] = ffma2(x2, wa.y, acc[j * 3 + 1]);
                acc[j * 3 + 2] = ffma2(x2, wb.x, acc[j * 3 + 2]);
            }
        }
        float* gout = g_gi + ((size_t)(t * NBLK + blk) * 64) * 96;
#pragma unroll
        for (int j = 0; j < 8; j++) {
            int jj = jbase + j;
#pragma unroll
            for (int m = 0; m < 3; m++)
                gout[jj * 96 + m * 32 + r] = sumh(acc[j * 3 + m]) + sbi[m * 64 + jj];
        }
    }
}

// ---------------- kernel 3: fused 2-layer GRU recurrence + classifier ----------------
// 512 threads / 16 warps, 4 hidden dims per warp, ONE barrier per phase
// (layer0 step t and layer1 step t-1 both read only p-buffers).
// smem: wb0 65536 | wb1 98304 | hb 32768 | bias0 1024 | bias1 1024 = 198656
#define SM_WB1 65536
#define SM_HB (65536 + 98304)
#define SM_B0 (SM_HB + 32768)
#define SM_B1 (SM_B0 + 1024)
#define SMEM_TOTAL (SM_B1 + 1024)

__global__ __launch_bounds__(512, 1) void k_gru(
    const float* __restrict__ Whh0, const float* __restrict__ bhh0,
    const float* __restrict__ Wih1, const float* __restrict__ Whh1,
    const float* __restrict__ bih1, const float* __restrict__ bhh1,
    const float* __restrict__ cW1, const float* __restrict__ cb1,
    const float* __restrict__ cW2, const float* __restrict__ cb2,
    float* __restrict__ out) {
    extern __shared__ char smc[];
    float2* wb0 = (float2*)smc;              // [j][kp][4] float2: Whh0 r,z,n,pad
    float2* wb1 = (float2*)(smc + SM_WB1);   // [j][kp][6] float2
    float2* hb = (float2*)(smc + SM_HB);     // 4 buffers of [kp][r] float2
    float4* bias0 = (float4*)(smc + SM_B0);
    float4* bias1 = (float4*)(smc + SM_B1);

    int tid = threadIdx.x;
    int r = tid & 31;
    int w = tid >> 5;        // 0..15
    int jbase = w * 4;       // 4 hidden dims per warp

    // ---- stage weights ----
    for (int i = tid; i < 64 * 32 * 4; i += 512) {
        int j = i >> 7, kp = (i >> 2) & 31, m = i & 3;
        float2 v = make_float2(0.f, 0.f);
        if (m < 3) {
            const float* src = Whh0 + (size_t)(m * 64 + j) * 64 + 2 * kp;
            v.x = src[0]; v.y = src[1];
        }
        wb0[i] = v;
    }
    for (int i = tid; i < 64 * 32 * 6; i += 512) {
        int m = i % 6;
        int kp = (i / 6) & 31;
        int j = i / 192;
        int g = (m >> 1) * 64 + j;
        const float* src = (m & 1) ? Whh1 : Wih1;
        float2 v;
        v.x = src[g * 64 + 2 * kp];
        v.y = src[g * 64 + 2 * kp + 1];
        wb1[i] = v;
    }
    if (tid < 64) {
        bias0[tid] = make_float4(bhh0[tid], bhh0[64 + tid], bhh0[128 + tid], 0.f);
        bias1[tid] = make_float4(bih1[tid] + bhh1[tid], bih1[64 + tid] + bhh1[64 + tid],
                                 bih1[128 + tid], bhh1[128 + tid]);
    }
    for (int i = tid; i < 4 * 1024; i += 512) hb[i] = make_float2(0.f, 0.f);
    __syncthreads();

    int blk = blockIdx.x;
    int rowbase = blk * 32;
    const float2* wl0 = wb0 + (size_t)jbase * 32 * 4;
    const float2* wl1 = wb1 + (size_t)jbase * 32 * 6;

    // prefetch gi for t=0
    float gcur[12];
    {
        const float* gp = g_gi + ((size_t)(0 * NBLK + blk) * 64) * 96 + r;
#pragma unroll
        for (int j = 0; j < 4; j++)
#pragma unroll
            for (int m = 0; m < 3; m++)
                gcur[j * 3 + m] = gp[(jbase + j) * 96 + m * 32];
    }

    int p = 0;
    for (int t = 0; t <= TT; t++) {
        // ===== layer 0, step t: h0[p] -> h0[p^1] =====
        if (t < TT) {
            unsigned long long aR[4], aZ[4], aN[4];
#pragma unroll
            for (int j = 0; j < 4; j++) { aR[j] = aZ[j] = aN[j] = 0ull; }
            const unsigned long long* h0p = (const unsigned long long*)(hb + p * 1024);
#pragma unroll
            for (int kp = 0; kp < 32; kp++) {
                unsigned long long h2 = h0p[kp * 32 + r];
#pragma unroll
                for (int j = 0; j < 4; j++) {
                    const ulonglong2* wp = (const ulonglong2*)(wl0 + (size_t)((j * 32 + kp) * 4));
                    ulonglong2 wa = wp[0];
                    ulonglong2 wb = wp[1];
                    aR[j] = ffma2(h2, wa.x, aR[j]);
                    aZ[j] = ffma2(h2, wa.y, aZ[j]);
                    aN[j] = ffma2(h2, wb.x, aN[j]);
                }
            }
            float* hnew = (float*)(hb + (p ^ 1) * 1024);
            const float* hold = (const float*)(hb + p * 1024);
#pragma unroll
            for (int j = 0; j < 4; j++) {
                int jj = jbase + j;
                float4 bv = bias0[jj];
                float rg = sigf(gcur[j * 3 + 0] + sumh(aR[j]) + bv.x);
                float zg = sigf(gcur[j * 3 + 1] + sumh(aZ[j]) + bv.y);
                float ng = tanhf_fast(gcur[j * 3 + 2] + rg * (sumh(aN[j]) + bv.z));
                float ho = hold[(jj >> 1) * 64 + r * 2 + (jj & 1)];
                hnew[(jj >> 1) * 64 + r * 2 + (jj & 1)] = ng + zg * (ho - ng);
            }
        }
        // prefetch gi for t+1
        if (t + 1 < TT) {
            const float* gp = g_gi + ((size_t)((t + 1) * NBLK + blk) * 64) * 96 + r;
#pragma unroll
            for (int j = 0; j < 4; j++)
#pragma unroll
                for (int m = 0; m < 3; m++)
                    gcur[j * 3 + m] = gp[(jbase + j) * 96 + m * 32];
        }
        // ===== layer 1, step t-1: x = h0[p] (= ys0[t-1]), h1[p] -> h1[p^1] =====
        if (t > 0) {
            unsigned long long ar[4], az[4], ai[4], ah[4];
#pragma unroll
            for (int j = 0; j < 4; j++) { ar[j] = az[j] = ai[j] = ah[j] = 0ull; }
            const unsigned long long* x1p = (const unsigned long long*)(hb + p * 1024);
            const unsigned long long* h1p = (const unsigned long long*)(hb + (2 + p) * 1024);
#pragma unroll
            for (int kp = 0; kp < 32; kp++) {
                unsigned long long x2 = x1p[kp * 32 + r];
                unsigned long long h2 = h1p[kp * 32 + r];
#pragma unroll
                for (int j = 0; j < 4; j++) {
                    const ulonglong2* wp = (const ulonglong2*)(wl1 + (size_t)((j * 32 + kp) * 6));
                    ulonglong2 wa = wp[0];
                    ulonglong2 wb = wp[1];
                    ulonglong2 wc = wp[2];
                    ar[j] = ffma2(x2, wa.x, ar[j]); ar[j] = ffma2(h2, wa.y, ar[j]);
                    az[j] = ffma2(x2, wb.x, az[j]); az[j] = ffma2(h2, wb.y, az[j]);
                    ai[j] = ffma2(x2, wc.x, ai[j]);
                    ah[j] = ffma2(h2, wc.y, ah[j]);
                }
            }
            float* hnew = (float*)(hb + (2 + (p ^ 1)) * 1024);
            const float* hold = (const float*)(hb + (2 + p) * 1024);
#pragma unroll
            for (int j = 0; j < 4; j++) {
                int jj = jbase + j;
                float4 bv = bias1[jj];
                float rg = sigf(sumh(ar[j]) + bv.x);
                float zg = sigf(sumh(az[j]) + bv.y);
                float ng = tanhf_fast(sumh(ai[j]) + bv.z + rg * (sumh(ah[j]) + bv.w));
                float ho = hold[(jj >> 1) * 64 + r * 2 + (jj & 1)];
                hnew[(jj >> 1) * 64 + r * 2 + (jj & 1)] = ng + zg * (ho - ng);
            }
        }
        __syncthreads();
        p ^= 1;
    }

    // ===== classifier: hid = relu(h1 @ cls_W1.T + b1) ; logits = hid @ cls_W2.T + b2 =====
    {
        unsigned long long acc[4];
#pragma unroll
        for (int j = 0; j < 4; j++) acc[j] = 0ull;
        const unsigned long long* h1p = (const unsigned long long*)(hb + (2 + p) * 1024);
#pragma unroll
        for (int kp = 0; kp < 32; kp++) {
            unsigned long long h2 = h1p[kp * 32 + r];
#pragma unroll
            for (int j = 0; j < 4; j++) {
                const unsigned long long* wp =
                    (const unsigned long long*)(cW1 + (jbase + j) * 64 + 2 * kp);
                acc[j] = ffma2(h2, *wp, acc[j]);
            }
        }
        float* hidb = (float*)(hb + (p ^ 1) * 1024);   // dead h0 buffer
#pragma unroll
        for (int j = 0; j < 4; j++) {
            int jj = jbase + j;
            float hv = fmaxf(sumh(acc[j]) + cb1[jj], 0.f);
            hidb[(jj >> 1) * 64 + r * 2 + (jj & 1)] = hv;
        }
    }
    __syncthreads();
    if (w < 8) {
        unsigned long long a = 0ull;
        const unsigned long long* hp = (const unsigned long long*)(hb + (p ^ 1) * 1024);
#pragma unroll
        for (int kp = 0; kp < 32; kp++) {
            const unsigned long long* wp = (const unsigned long long*)(cW2 + w * 64 + 2 * kp);
            a = ffma2(hp[kp * 32 + r], *wp, a);
        }
        out[(rowbase + r) * 8 + w] = sumh(a) + cb2[w];
    }
}

// ---------------- launch ----------------
extern "C" void kernel_launch(void* const* d_in, const int* in_sizes, int n_in,
                              void* d_out, int out_size) {
    const float* obs  = (const float*)d_in[0];
    const int*   act  = (const int*)d_in[1];
    const float* pW   = (const float*)d_in[2];
    const float* pb   = (const float*)d_in[3];
    const float* lg   = (const float*)d_in[4];
    const float* lb   = (const float*)d_in[5];
    const float* Wih0 = (const float*)d_in[6];
    const float* Whh0 = (const float*)d_in[7];
    const float* bih0 = (const float*)d_in[8];
    const float* bhh0 = (const float*)d_in[9];
    const float* Wih1 = (const float*)d_in[10];
    const float* Whh1 = (const float*)d_in[11];
    const float* bih1 = (const float*)d_in[12];
    const float* bhh1 = (const float*)d_in[13];
    const float* cW1  = (const float*)d_in[14];
    const float* cb1  = (const float*)d_in[15];
    const float* cW2  = (const float*)d_in[16];
    const float* cb2  = (const float*)d_in[17];
    float* out = (float*)d_out;

    cudaFuncSetAttribute(k_feat, cudaFuncAttributeMaxDynamicSharedMemorySize, KF_SMEM);
    cudaFuncSetAttribute(k_gi0, cudaFuncAttributeMaxDynamicSharedMemorySize, GI_SMEM);
    cudaFuncSetAttribute(k_gru, cudaFuncAttributeMaxDynamicSharedMemorySize, SMEM_TOTAL);

    k_feat<<<512, 256, KF_SMEM>>>(obs, act, pW, pb, lg, lb);
    k_gi0<<<512, 256, GI_SMEM>>>(Wih0, bih0);
    k_gru<<<NBLK, 512, SMEM_TOTAL>>>(Whh0, bhh0,
                                     Wih1, Whh1, bih1, bhh1,
                                     cW1, cb1, cW2, cb2, out);
}